// round 1
// baseline (speedup 1.0000x reference)
#include <cuda_runtime.h>
#include <cstdint>

// Submanifold sparse conv as rulebook gather -> per-offset 16x16 GEMV -> scatter-add.
// features: [N,16] f32, weight: [27,16,16] f32, bias: [16] f32,
// rules_in/rules_out: [27,R] i32. out: [N,16] f32.

constexpr int KOFF = 27;
constexpr int CIN  = 16;
constexpr int COUT = 16;

__global__ void init_bias_kernel(float* __restrict__ out,
                                 const float* __restrict__ bias,
                                 int n_total /* N*COUT */) {
    int i = blockIdx.x * blockDim.x + threadIdx.x;
    if (i < n_total) {
        out[i] = bias[i & (COUT - 1)];
    }
}

__global__ void __launch_bounds__(256)
subconv_kernel(const float4* __restrict__ feat4,   // [N*4] float4 (N rows x 16 f32)
               const float*  __restrict__ weight,  // [27*256]
               const int*    __restrict__ rin,     // [27*R]
               const int*    __restrict__ rout,    // [27*R]
               float*        __restrict__ out,     // [N*16]
               int R) {
    // weight tile for this offset, laid out [c][o/4] as float4
    __shared__ float4 wsh[CIN * (COUT / 4)];

    const int k = blockIdx.y;
    if (threadIdx.x < CIN * (COUT / 4)) {
        wsh[threadIdx.x] =
            reinterpret_cast<const float4*>(weight + k * CIN * COUT)[threadIdx.x];
    }
    __syncthreads();

    const int r = blockIdx.x * blockDim.x + threadIdx.x;
    if (r >= R) return;

    const long base = (long)k * R + r;
    const int ii = rin[base];
    const int io = rout[base];

    // Gather one feature row (16 f32 = 4 float4)
    const float4 f0 = feat4[(long)ii * 4 + 0];
    const float4 f1 = feat4[(long)ii * 4 + 1];
    const float4 f2 = feat4[(long)ii * 4 + 2];
    const float4 f3 = feat4[(long)ii * 4 + 3];

    float f[CIN];
    *reinterpret_cast<float4*>(&f[0])  = f0;
    *reinterpret_cast<float4*>(&f[4])  = f1;
    *reinterpret_cast<float4*>(&f[8])  = f2;
    *reinterpret_cast<float4*>(&f[12]) = f3;

    float4 a0 = make_float4(0.f, 0.f, 0.f, 0.f);
    float4 a1 = a0, a2 = a0, a3 = a0;

#pragma unroll
    for (int c = 0; c < CIN; ++c) {
        const float fc = f[c];
        const float4 w0 = wsh[c * 4 + 0];
        const float4 w1 = wsh[c * 4 + 1];
        const float4 w2 = wsh[c * 4 + 2];
        const float4 w3 = wsh[c * 4 + 3];
        a0.x += fc * w0.x; a0.y += fc * w0.y; a0.z += fc * w0.z; a0.w += fc * w0.w;
        a1.x += fc * w1.x; a1.y += fc * w1.y; a1.z += fc * w1.z; a1.w += fc * w1.w;
        a2.x += fc * w2.x; a2.y += fc * w2.y; a2.z += fc * w2.z; a2.w += fc * w2.w;
        a3.x += fc * w3.x; a3.y += fc * w3.y; a3.z += fc * w3.z; a3.w += fc * w3.w;
    }

    // Scatter-add 16 f32 via 4 vector reductions (fire-and-forget, sm_90+)
    float* op = out + (long)io * COUT;
    asm volatile("red.global.add.v4.f32 [%0], {%1,%2,%3,%4};"
                 :: "l"(op +  0), "f"(a0.x), "f"(a0.y), "f"(a0.z), "f"(a0.w)
                 : "memory");
    asm volatile("red.global.add.v4.f32 [%0], {%1,%2,%3,%4};"
                 :: "l"(op +  4), "f"(a1.x), "f"(a1.y), "f"(a1.z), "f"(a1.w)
                 : "memory");
    asm volatile("red.global.add.v4.f32 [%0], {%1,%2,%3,%4};"
                 :: "l"(op +  8), "f"(a2.x), "f"(a2.y), "f"(a2.z), "f"(a2.w)
                 : "memory");
    asm volatile("red.global.add.v4.f32 [%0], {%1,%2,%3,%4};"
                 :: "l"(op + 12), "f"(a3.x), "f"(a3.y), "f"(a3.z), "f"(a3.w)
                 : "memory");
}

extern "C" void kernel_launch(void* const* d_in, const int* in_sizes, int n_in,
                              void* d_out, int out_size) {
    const float* features = (const float*)d_in[0];   // [N*16]
    const float* weight   = (const float*)d_in[1];   // [27*16*16]
    const float* bias     = (const float*)d_in[2];   // [16]
    const int*   rules_in = (const int*)d_in[3];     // [27*R]
    const int*   rules_out= (const int*)d_in[4];     // [27*R]
    float* out = (float*)d_out;                      // [N*16]

    const int N = in_sizes[0] / CIN;
    const int R = in_sizes[3] / KOFF;
    const int n_total = N * COUT;

    // 1) out = bias broadcast
    {
        const int threads = 256;
        const int blocks = (n_total + threads - 1) / threads;
        init_bias_kernel<<<blocks, threads>>>(out, bias, n_total);
    }

    // 2) gather -> GEMV -> scatter-add
    {
        const int threads = 256;
        dim3 grid((R + threads - 1) / threads, KOFF);
        subconv_kernel<<<grid, threads>>>(
            reinterpret_cast<const float4*>(features),
            weight, rules_in, rules_out, out, R);
    }
}